// round 3
// baseline (speedup 1.0000x reference)
#include <cuda_runtime.h>

#define HH   128
#define WW   256
#define NN   4
#define CIN  64
#define COUT 128
#define KTOT 576          // 9 taps * 64 channels
#define PP   16           // pixels per block

// Scratch (static device globals — no runtime allocation)
__device__ float  g_xt[NN * HH * WW * CIN];   // x transposed to [n][y][x][ci] (33.5 MB, fits L2)
__device__ float  g_wT[KTOT * COUT];          // weight transposed to [k][co], k = tap*64+ci
__device__ float2 g_grid[HH * WW * 9];        // (ix, iy) unnormalized sample coords per (r,c,tap)

// ---------------------------------------------------------------------------
// Kernel 1: spherical sampling grid in fp64 (matches numpy fp64 -> fp32 cast)
// ---------------------------------------------------------------------------
__global__ void grid_kernel() {
    int idx = blockIdx.x * blockDim.x + threadIdx.x;
    if (idx >= HH * WW) return;
    int r = idx / WW, c = idx % WW;
    const double PI = 3.141592653589793238462643383279502884;
    double dphi = PI / HH, dth = 2.0 * PI / WW;
    double tt = tan(dth), pq = tan(dphi), sp = pq / cos(dth);
    double phi   = -(((double)r + 0.5) / HH * PI - PI * 0.5);
    double theta = ((double)c + 0.5) / WW * 2.0 * PI - PI;
    double sphi = sin(phi), cphi = cos(phi);
    #pragma unroll
    for (int i = 0; i < 3; i++) {
        #pragma unroll
        for (int j = 0; j < 3; j++) {
            double nr, nc;
            if (i == 1 && j == 1) {
                nr = (double)r; nc = (double)c;   // center tap: exact identity (per reference)
            } else {
                double X = (j == 0) ? -tt : (j == 2) ? tt : 0.0;
                double Y;
                if (i == 0)      Y = (j == 1) ?  pq :  sp;
                else if (i == 2) Y = (j == 1) ? -pq : -sp;
                else             Y = 0.0;
                double rho = sqrt(X * X + Y * Y);
                double v   = atan(rho);
                double sv  = sin(v), cv = cos(v);
                double arg = cv * sphi + Y * sv * cphi / rho;
                arg = fmin(1.0, fmax(-1.0, arg));
                double nphi   = asin(arg);
                double ntheta = theta + atan((X * sv) / (rho * cphi * cv - Y * sphi * sv));
                nr = (-nphi + PI * 0.5) * HH / PI - 0.5;
                nc = (ntheta + PI) * WW / (2.0 * PI) - 0.5;
                nc = fmod(nc + (double)WW, (double)WW);
            }
            // reference casts grid to fp32, then unnormalizes in fp32
            float gx = (float)(nc * 2.0 / WW - 1.0);
            float gy = (float)(nr * 2.0 / HH - 1.0);
            float ix = ((gx + 1.0f) * WW - 1.0f) * 0.5f;
            float iy = ((gy + 1.0f) * HH - 1.0f) * 0.5f;
            g_grid[idx * 9 + i * 3 + j] = make_float2(ix, iy);
        }
    }
}

// ---------------------------------------------------------------------------
// Kernel 2: weight transpose  wT[k][co],  k = tap*64 + ci
// ---------------------------------------------------------------------------
__global__ void wt_kernel(const float* __restrict__ w) {
    int i = blockIdx.x * blockDim.x + threadIdx.x;
    if (i >= KTOT * COUT) return;
    int k = i / COUT, co = i % COUT;
    int tap = k / CIN, ci = k % CIN;
    g_wT[i] = w[(co * CIN + ci) * 9 + tap];
}

// ---------------------------------------------------------------------------
// Kernel 3: x -> channels-last transpose via shared-memory tiles
// ---------------------------------------------------------------------------
__global__ void xt_kernel(const float* __restrict__ x) {
    __shared__ float tile[CIN][33];
    int b  = blockIdx.x;
    int x0 = (b % (WW / 32)) * 32;
    int ny = b / (WW / 32);         // n*HH + y
    for (int i = threadIdx.x; i < CIN * 32; i += 256) {
        int ci = i >> 5, xx = i & 31;
        tile[ci][xx] = x[((size_t)(ny / HH * CIN + ci) * HH + (ny % HH)) * WW + x0 + xx];
    }
    __syncthreads();
    for (int i = threadIdx.x; i < CIN * 32; i += 256) {
        int xx = i >> 6, ci = i & 63;
        g_xt[((size_t)ny * WW + x0 + xx) * CIN + ci] = tile[ci][xx];
    }
}

// ---------------------------------------------------------------------------
// Kernel 4: fused bilinear-gather + 128x16x576 matvec
// ---------------------------------------------------------------------------
__global__ __launch_bounds__(128) void main_kernel(const float* __restrict__ bias,
                                                   float* __restrict__ out) {
    __shared__ float s_sh[KTOT][PP];   // 36864 B; [k][p], k = tap*64+ci
    const int blk  = blockIdx.x;
    const int pix0 = blk * PP;                 // global pixel id n*H*W + r*W + c
    const int n    = pix0 >> 15;               // H*W = 32768
    const int rc0  = pix0 & (HH * WW - 1);
    const int t    = threadIdx.x;
    const float* __restrict__ xbase = g_xt + (size_t)n * HH * WW * CIN;

    // ---- Stage 1: gather sampled tile into shared -------------------------
    // task space: 9 taps * 16 pixels * 16 channel-quads = 2304 tasks
    for (int task = t; task < 9 * PP * 16; task += 128) {
        int p   = task & 15;
        int q   = task >> 4;       // 0..143
        int g4  = q & 15;          // channel quad
        int tap = q >> 4;          // 0..8
        float2 g = g_grid[(rc0 + p) * 9 + tap];
        float ix = g.x, iy = g.y;
        float fx = floorf(ix), fy = floorf(iy);
        int   x0 = (int)fx, y0 = (int)fy;
        float wx1 = ix - fx, wy1 = iy - fy;
        float wx0 = 1.0f - wx1, wy0 = 1.0f - wy1;
        float mx0 = (x0 >= 0 && x0 < WW)         ? 1.f : 0.f;
        float mx1 = (x0 + 1 >= 0 && x0 + 1 < WW) ? 1.f : 0.f;
        float my0 = (y0 >= 0 && y0 < HH)         ? 1.f : 0.f;
        float my1 = (y0 + 1 >= 0 && y0 + 1 < HH) ? 1.f : 0.f;
        float w00 = wy0 * wx0 * (my0 * mx0);
        float w01 = wy0 * wx1 * (my0 * mx1);
        float w10 = wy1 * wx0 * (my1 * mx0);
        float w11 = wy1 * wx1 * (my1 * mx1);
        int xc0 = min(max(x0, 0), WW - 1);
        int xc1 = min(max(x0 + 1, 0), WW - 1);
        int yc0 = min(max(y0, 0), HH - 1);
        int yc1 = min(max(y0 + 1, 0), HH - 1);
        int o = g4 << 2;
        const float4 v00 = *(const float4*)(xbase + ((size_t)yc0 * WW + xc0) * CIN + o);
        const float4 v01 = *(const float4*)(xbase + ((size_t)yc0 * WW + xc1) * CIN + o);
        const float4 v10 = *(const float4*)(xbase + ((size_t)yc1 * WW + xc0) * CIN + o);
        const float4 v11 = *(const float4*)(xbase + ((size_t)yc1 * WW + xc1) * CIN + o);
        int k = tap * CIN + o;
        s_sh[k + 0][p] = v00.x * w00 + v01.x * w01 + v10.x * w10 + v11.x * w11;
        s_sh[k + 1][p] = v00.y * w00 + v01.y * w01 + v10.y * w10 + v11.y * w11;
        s_sh[k + 2][p] = v00.z * w00 + v01.z * w01 + v10.z * w10 + v11.z * w11;
        s_sh[k + 3][p] = v00.w * w00 + v01.w * w01 + v10.w * w10 + v11.w * w11;
    }
    __syncthreads();

    // ---- Stage 2: matvec over k: out[co][p] = sum_k wT[k][co] * s[k][p] ----
    const int co = t;
    float acc[PP];
    float bv = bias[co];
    #pragma unroll
    for (int p = 0; p < PP; p++) acc[p] = bv;
    const float* __restrict__ wp = g_wT + co;
    #pragma unroll 4
    for (int k = 0; k < KTOT; k++) {
        float wv = wp[(size_t)k * COUT];
        const float4* srow = (const float4*)&s_sh[k][0];
        float4 s0 = srow[0], s1 = srow[1], s2 = srow[2], s3 = srow[3];
        acc[0]  = fmaf(wv, s0.x, acc[0]);
        acc[1]  = fmaf(wv, s0.y, acc[1]);
        acc[2]  = fmaf(wv, s0.z, acc[2]);
        acc[3]  = fmaf(wv, s0.w, acc[3]);
        acc[4]  = fmaf(wv, s1.x, acc[4]);
        acc[5]  = fmaf(wv, s1.y, acc[5]);
        acc[6]  = fmaf(wv, s1.z, acc[6]);
        acc[7]  = fmaf(wv, s1.w, acc[7]);
        acc[8]  = fmaf(wv, s2.x, acc[8]);
        acc[9]  = fmaf(wv, s2.y, acc[9]);
        acc[10] = fmaf(wv, s2.z, acc[10]);
        acc[11] = fmaf(wv, s2.w, acc[11]);
        acc[12] = fmaf(wv, s3.x, acc[12]);
        acc[13] = fmaf(wv, s3.y, acc[13]);
        acc[14] = fmaf(wv, s3.z, acc[14]);
        acc[15] = fmaf(wv, s3.w, acc[15]);
    }
    __syncthreads();

    // ---- Stage 3: stage results through shared for coalesced output -------
    float* s2m = &s_sh[0][0];                 // reuse (needs 128*18 = 2304 floats)
    #pragma unroll
    for (int p = 0; p < PP; p++) s2m[co * 18 + p] = acc[p];
    __syncthreads();

    const int r  = rc0 >> 8;                  // / WW
    const int c0 = rc0 & 255;
    float* op = out + ((size_t)n * COUT) * HH * WW + (size_t)r * WW + c0;
    for (int i = t; i < COUT * PP; i += 128) {
        int p = i & 15, co2 = i >> 4;
        op[(size_t)co2 * HH * WW + p] = s2m[co2 * 18 + p];
    }
}

// ---------------------------------------------------------------------------
extern "C" void kernel_launch(void* const* d_in, const int* in_sizes, int n_in,
                              void* d_out, int out_size) {
    const float* x = (const float*)d_in[0];
    const float* w = (const float*)d_in[1];
    const float* b = (const float*)d_in[2];
    float* out = (float*)d_out;

    grid_kernel<<<(HH * WW + 127) / 128, 128>>>();
    wt_kernel<<<(KTOT * COUT + 255) / 256, 256>>>(w);
    xt_kernel<<<NN * HH * (WW / 32), 256>>>(x);
    main_kernel<<<NN * HH * WW / PP, 128>>>(b, out);
}

// round 8
// speedup vs baseline: 2.1534x; 2.1534x over previous
#include <cuda_runtime.h>
#include <cstdint>

#define HH   128
#define WW   256
#define NN   4
#define CIN  64
#define COUT 128
#define HWSZ (HH * WW)
#define PP   128          // pixels per CTA
#define NTAP 9

typedef unsigned long long u64;

// Scratch (static device globals — no runtime allocation)
__device__ float  g_xt[NN * HH * WW * CIN];   // x transposed to [n][y][x][ci]
__device__ float  g_wT[NTAP * CIN * COUT];    // weight [k][co], k = tap*64+ci
__device__ float2 g_grid[HH * WW * NTAP];     // (ix, iy) unnormalized sample coords
__device__ double g_nrd[HH * NTAP];           // per (row, tap): new_r (fp64)
__device__ double g_dcd[HH * NTAP];           // per (row, tap): delta-col (fp64)

// f32x2 packed FMA (Blackwell family-level PTX)
#define FMA2(d, a, b) \
    asm("fma.rn.f32x2 %0, %1, %2, %3;" : "=l"(d) : "l"(a), "l"(b), "l"(d))
#define PACK2(d, x) \
    asm("mov.b64 %0, {%1, %1};" : "=l"(d) : "r"(x))

// ---------------------------------------------------------------------------
// Kernel 1a: heavy fp64 trig, only (row, tap)-dependent  (1152 points)
// ---------------------------------------------------------------------------
__global__ void grid1_kernel() {
    int idx = blockIdx.x * blockDim.x + threadIdx.x;
    if (idx >= HH * NTAP) return;
    int r = idx / NTAP, t = idx % NTAP;
    int i = t / 3, j = t % 3;
    const double PI = 3.141592653589793238462643383279502884;
    if (i == 1 && j == 1) {                 // center tap: exact identity
        g_nrd[idx] = (double)r;
        g_dcd[idx] = 0.0;
        return;
    }
    double dphi = PI / HH, dth = 2.0 * PI / WW;
    double tt = tan(dth), pq = tan(dphi), sp = pq / cos(dth);
    double phi = -(((double)r + 0.5) / HH * PI - PI * 0.5);
    double sphi = sin(phi), cphi = cos(phi);
    double X = (j == 0) ? -tt : (j == 2) ? tt : 0.0;
    double Y;
    if (i == 0)      Y = (j == 1) ?  pq :  sp;
    else if (i == 2) Y = (j == 1) ? -pq : -sp;
    else             Y = 0.0;
    double rho = sqrt(X * X + Y * Y);
    double v   = atan(rho);
    double sv  = sin(v), cv = cos(v);
    double arg = cv * sphi + Y * sv * cphi / rho;
    arg = fmin(1.0, fmax(-1.0, arg));
    double nphi = asin(arg);
    double A    = atan((X * sv) / (rho * cphi * cv - Y * sphi * sv));
    g_nrd[idx] = (-nphi + PI * 0.5) * HH / PI - 0.5;
    g_dcd[idx] = A * WW / (2.0 * PI);       // new_c = c + dcd  (theta terms cancel)
}

// ---------------------------------------------------------------------------
// Kernel 1b: expand to full grid (cheap fp64 adds + fp32 cast)
// ---------------------------------------------------------------------------
__global__ void grid2_kernel() {
    int idx = blockIdx.x * blockDim.x + threadIdx.x;
    if (idx >= HWSZ * NTAP) return;
    int p = idx / NTAP, t = idx % NTAP;
    int r = p >> 8, c = p & 255;
    double nr = g_nrd[r * NTAP + t];
    double nc = fmod((double)c + g_dcd[r * NTAP + t] + (double)WW, (double)WW);
    float gx = (float)(nc * 2.0 / WW - 1.0);
    float gy = (float)(nr * 2.0 / HH - 1.0);
    float ix = ((gx + 1.0f) * WW - 1.0f) * 0.5f;
    float iy = ((gy + 1.0f) * HH - 1.0f) * 0.5f;
    g_grid[idx] = make_float2(ix, iy);
}

// ---------------------------------------------------------------------------
// Kernel 2: weight transpose  wT[k][co],  k = tap*64 + ci
// ---------------------------------------------------------------------------
__global__ void wt_kernel(const float* __restrict__ w) {
    int i = blockIdx.x * blockDim.x + threadIdx.x;
    if (i >= NTAP * CIN * COUT) return;
    int k = i >> 7, co = i & 127;
    int tap = k / CIN, ci = k % CIN;
    g_wT[i] = w[(co * CIN + ci) * 9 + tap];
}

// ---------------------------------------------------------------------------
// Kernel 3: x -> channels-last transpose via shared-memory tiles
// ---------------------------------------------------------------------------
__global__ void xt_kernel(const float* __restrict__ x) {
    __shared__ float tile[CIN][33];
    int b  = blockIdx.x;
    int x0 = (b % (WW / 32)) * 32;
    int ny = b / (WW / 32);
    for (int i = threadIdx.x; i < CIN * 32; i += 256) {
        int ci = i >> 5, xx = i & 31;
        tile[ci][xx] = x[((size_t)(ny / HH * CIN + ci) * HH + (ny % HH)) * WW + x0 + xx];
    }
    __syncthreads();
    for (int i = threadIdx.x; i < CIN * 32; i += 256) {
        int xx = i >> 6, ci = i & 63;
        g_xt[((size_t)ny * WW + x0 + xx) * CIN + ci] = tile[ci][xx];
    }
}

// ---------------------------------------------------------------------------
// Kernel 4: fused gather + register-blocked f32x2 matmul
//   smem: [0, 32K)  w_s[64][128] floats (per-tap weight slab)
//         [32K,64K) s_s[64][128] floats, XOR-swizzled 16B units
//   thread tile: 16 co (co0 = wid*16) x 4 px (px0 = lane*4)
// ---------------------------------------------------------------------------
#define SMEM_TOTAL 65536

__global__ __launch_bounds__(256, 2) void main_kernel(const float* __restrict__ bias,
                                                      float* __restrict__ out) {
    extern __shared__ char smem[];
    char* sw = smem;                 // weights:  k*512 + u*16
    char* ss = smem + 32768;         // samples:  ch*512 + unit*16 + (px&3)*4
    const int tid  = threadIdx.x;
    const int wid  = tid >> 5, lane = tid & 31;
    const int pix0 = blockIdx.x << 7;
    const int n    = pix0 >> 15;
    const int rc0  = pix0 & (HWSZ - 1);
    const int qlo  = lane & 7;       // quad-low (gather)
    const int pm   = lane >> 3;      // px sub   (gather)
    const int co0  = wid << 4;

    const float* __restrict__ xb = g_xt + (size_t)n * (HWSZ * CIN);

    u64 acc[8][4];
    #pragma unroll
    for (int cp = 0; cp < 8; cp++)
        #pragma unroll
        for (int m = 0; m < 4; m++) acc[cp][m] = 0ULL;

    for (int tap = 0; tap < NTAP; tap++) {
        // ---- stage A1: weight slab  w_s[k][co] = g_wT[tap*64+k][co] -------
        #pragma unroll
        for (int it = 0; it < 8; it++) {
            int e = tid + it * 256;          // float4 units, 2048 total
            int k = e >> 5, u = e & 31;
            float4 wv = *(const float4*)(g_wT + ((size_t)(tap * CIN + k) << 7) + (u << 2));
            *(float4*)(sw + (k << 9) + (u << 4)) = wv;
        }

        // ---- stage A2: bilinear gather into swizzled s_s -------------------
        #pragma unroll
        for (int pxi = 0; pxi < 4; pxi++) {
            int px  = (wid << 4) + (pxi << 2) + pm;
            float2 g = g_grid[(rc0 + px) * NTAP + tap];
            float ix = g.x, iy = g.y;
            float fx = floorf(ix), fy = floorf(iy);
            int   x0 = (int)fx, y0 = (int)fy;
            float wx1 = ix - fx, wy1 = iy - fy;
            float wx0 = 1.0f - wx1, wy0 = 1.0f - wy1;
            float mx0 = (x0 >= 0 && x0 < WW)         ? 1.f : 0.f;
            float mx1 = (x0 + 1 >= 0 && x0 + 1 < WW) ? 1.f : 0.f;
            float my0 = (y0 >= 0 && y0 < HH)         ? 1.f : 0.f;
            float my1 = (y0 + 1 >= 0 && y0 + 1 < HH) ? 1.f : 0.f;
            float w00 = wy0 * wx0 * (my0 * mx0);
            float w01 = wy0 * wx1 * (my0 * mx1);
            float w10 = wy1 * wx0 * (my1 * mx0);
            float w11 = wy1 * wx1 * (my1 * mx1);
            int xc0 = min(max(x0, 0), WW - 1);
            int xc1 = min(max(x0 + 1, 0), WW - 1);
            int yc0 = min(max(y0, 0), HH - 1);
            int yc1 = min(max(y0 + 1, 0), HH - 1);
            const float* b00 = xb + (yc0 * WW + xc0) * CIN;
            const float* b01 = xb + (yc0 * WW + xc1) * CIN;
            const float* b10 = xb + (yc1 * WW + xc0) * CIN;
            const float* b11 = xb + (yc1 * WW + xc1) * CIN;
            int unit = ((px >> 2) ^ qlo);     // swizzle: f(ch) = (ch>>2)&7 = q&7 = qlo
            #pragma unroll
            for (int qhi = 0; qhi < 2; qhi++) {
                int q  = qlo + (qhi << 3);    // quad 0..15
                int o  = q << 2;              // channel base
                float4 v00 = *(const float4*)(b00 + o);
                float4 v01 = *(const float4*)(b01 + o);
                float4 v10 = *(const float4*)(b10 + o);
                float4 v11 = *(const float4*)(b11 + o);
                float r0 = v00.x * w00 + v01.x * w01 + v10.x * w10 + v11.x * w11;
                float r1 = v00.y * w00 + v01.y * w01 + v10.y * w10 + v11.y * w11;
                float r2 = v00.z * w00 + v01.z * w01 + v10.z * w10 + v11.z * w11;
                float r3 = v00.w * w00 + v01.w * w01 + v10.w * w10 + v11.w * w11;
                char* base = ss + (unit << 4) + ((px & 3) << 2);
                *(float*)(base + ((o + 0) << 9)) = r0;
                *(float*)(base + ((o + 1) << 9)) = r1;
                *(float*)(base + ((o + 2) << 9)) = r2;
                *(float*)(base + ((o + 3) << 9)) = r3;
            }
        }
        __syncthreads();

        // ---- stage B: 64 k-steps, 16co x 4px per thread, f32x2 -------------
        const char* wbase = sw + (co0 << 2);          // + k*512
        #pragma unroll 2
        for (int k = 0; k < CIN; k++) {
            // weights: 16 consecutive co as 8 packed pairs (broadcast loads)
            ulonglong2 q0 = *(const ulonglong2*)(wbase + (k << 9));
            ulonglong2 q1 = *(const ulonglong2*)(wbase + (k << 9) + 16);
            ulonglong2 q2 = *(const ulonglong2*)(wbase + (k << 9) + 32);
            ulonglong2 q3 = *(const ulonglong2*)(wbase + (k << 9) + 48);
            // samples: this thread's 4 px (swizzled, conflict-free)
            int f = (k >> 2) & 7;
            float4 sv = *(const float4*)(ss + (k << 9) + ((lane ^ f) << 4));
            u64 sd0, sd1, sd2, sd3;
            PACK2(sd0, __float_as_uint(sv.x));
            PACK2(sd1, __float_as_uint(sv.y));
            PACK2(sd2, __float_as_uint(sv.z));
            PACK2(sd3, __float_as_uint(sv.w));
            u64 wp[8] = {q0.x, q0.y, q1.x, q1.y, q2.x, q2.y, q3.x, q3.y};
            #pragma unroll
            for (int cp = 0; cp < 8; cp++) {
                FMA2(acc[cp][0], wp[cp], sd0);
                FMA2(acc[cp][1], wp[cp], sd1);
                FMA2(acc[cp][2], wp[cp], sd2);
                FMA2(acc[cp][3], wp[cp], sd3);
            }
        }
        __syncthreads();   // protect smem before next tap overwrites
    }

    // ---- epilogue: unpack, add bias, coalesced float4 stores ---------------
    float* outp = out + (size_t)n * COUT * HWSZ + rc0 + (lane << 2);
    #pragma unroll
    for (int cp = 0; cp < 8; cp++) {
        int ca = co0 + (cp << 1), cb = ca + 1;
        float ba = __ldg(&bias[ca]), bb = __ldg(&bias[cb]);
        float4 fa, fb;
        fa.x = __uint_as_float((uint32_t)acc[cp][0]) + ba;
        fa.y = __uint_as_float((uint32_t)acc[cp][1]) + ba;
        fa.z = __uint_as_float((uint32_t)acc[cp][2]) + ba;
        fa.w = __uint_as_float((uint32_t)acc[cp][3]) + ba;
        fb.x = __uint_as_float((uint32_t)(acc[cp][0] >> 32)) + bb;
        fb.y = __uint_as_float((uint32_t)(acc[cp][1] >> 32)) + bb;
        fb.z = __uint_as_float((uint32_t)(acc[cp][2] >> 32)) + bb;
        fb.w = __uint_as_float((uint32_t)(acc[cp][3] >> 32)) + bb;
        *(float4*)(outp + (size_t)ca * HWSZ) = fa;
        *(float4*)(outp + (size_t)cb * HWSZ) = fb;
    }
}

// ---------------------------------------------------------------------------
extern "C" void kernel_launch(void* const* d_in, const int* in_sizes, int n_in,
                              void* d_out, int out_size) {
    const float* x = (const float*)d_in[0];
    const float* w = (const float*)d_in[1];
    const float* b = (const float*)d_in[2];
    float* out = (float*)d_out;

    cudaFuncSetAttribute(main_kernel,
                         cudaFuncAttributeMaxDynamicSharedMemorySize, SMEM_TOTAL);

    grid1_kernel<<<(HH * NTAP + 127) / 128, 128>>>();
    grid2_kernel<<<(HWSZ * NTAP + 255) / 256, 256>>>();
    wt_kernel<<<(NTAP * CIN * COUT + 255) / 256, 256>>>(w);
    xt_kernel<<<NN * HH * (WW / 32), 256>>>(x);
    main_kernel<<<NN * HWSZ / PP, 256, SMEM_TOTAL>>>(b, out);
}